// round 3
// baseline (speedup 1.0000x reference)
#include <cuda_runtime.h>
#include <math.h>

#define SLEN 1024
#define NM   32
#define HID  128
#define NB   1024

// ---------------- scratch (static device memory; no allocation) ----------------
__device__ float g_tabC[SLEN*NM];          // cos(2*pi*m*s/S), [s][m]
__device__ float g_tabS[SLEN*NM];          // sin(2*pi*m*s/S), [s][m]
__device__ float g_w1tr[NM*HID];           // [m][ch]
__device__ float g_w1ti[NM*HID];
__device__ float g_w2tr[NM*HID*HID];       // [m][i][o]
__device__ float g_w2ti[NM*HID*HID];
__device__ float g_Zf [2*NM*NB*HID];       // [(m*2+ri)][b][ch]
__device__ float g_of2[2*NM*NB*HID];       // [(m*2+ri)][b][o]

__device__ __forceinline__ float gelu_exact(float x) {
    return 0.5f * x * (1.0f + erff(x * 0.70710678118654752f));
}

// ---------------- K_tab: exact trig tables ----------------
__global__ void k_tab() {
    int idx = blockIdx.x * blockDim.x + threadIdx.x;
    if (idx >= SLEN * NM) return;
    int s = idx >> 5, m = idx & 31;
    int k = (s * m) & (SLEN - 1);              // exact phase reduction
    float x = (float)k * (1.0f / 512.0f);      // angle = pi * x = 2*pi*k/1024
    float sv, cv;
    sincospif(x, &sv, &cv);
    g_tabC[idx] = cv;
    g_tabS[idx] = sv;
}

// ---------------- K_w: weight transposes ----------------
__global__ void k_w(const float* __restrict__ w1r, const float* __restrict__ w1i,
                    const float* __restrict__ w2r, const float* __restrict__ w2i) {
    int tid = blockIdx.x * blockDim.x + threadIdx.x;
    if (tid < NM * HID) {                      // w1 src: [ch][m]
        int ch = tid >> 5, m = tid & 31;
        g_w1tr[m * HID + ch] = w1r[tid];
        g_w1ti[m * HID + ch] = w1i[tid];
    }
    if (tid < NM * HID * HID) {                // w2 src: [i][o][m]
        int m = tid & 31; int io = tid >> 5;
        int i = io >> 7;  int o = io & 127;
        g_w2tr[(m * HID + i) * HID + o] = w2r[tid];
        g_w2ti[(m * HID + i) * HID + o] = w2i[tid];
    }
}

// ---------------- K_layer1: DFT(h) -> mix w1 -> synth+gelu+analyze (fused) ----------------
// Block = one batch row b. 256 threads.
// Warp w handles channels [16w, 16w+16); lane>>4 selects mode-half (16 modes each).
__global__ __launch_bounds__(256, 2) void k_layer1(const float* __restrict__ hin) {
    __shared__ float h_sm[SLEN];
    __shared__ float red[64 * 4];
    __shared__ float Hf[64];                   // [0:32) real, [32:64) imag
    int b = blockIdx.x;
    int t = threadIdx.x;

    // stage h row
    {
        const float4* src = reinterpret_cast<const float4*>(hin + (size_t)b * SLEN);
        float4* dst = reinterpret_cast<float4*>(h_sm);
        for (int j = t; j < SLEN / 4; j += 256) dst[j] = src[j];
    }
    __syncthreads();

    // forward DFT of h: Hfr[m] = sum h*cos, Hfi[m] = -sum h*sin
    {
        int out = t & 63, seg = t >> 6;
        int m = out & 31; int isI = out >> 5;
        const float* tab = isI ? g_tabS : g_tabC;
        float acc = 0.0f;
        int s0 = seg * 256;
        #pragma unroll 8
        for (int j = 0; j < 256; j++) {
            int s = s0 + j;
            acc = fmaf(h_sm[s], __ldg(&tab[s * NM + m]), acc);
        }
        red[out * 4 + seg] = acc;
    }
    __syncthreads();
    if (t < 64) {
        float v = red[t * 4] + red[t * 4 + 1] + red[t * 4 + 2] + red[t * 4 + 3];
        Hf[t] = (t >= 32) ? -v : v;
    }
    __syncthreads();

    int lane = t & 31;
    int w    = t >> 5;
    int hh   = lane >> 4;                      // mode-half
    int ch   = w * 16 + (lane & 15);

    // synthesis coefficients: y(s) = sum ar[m]*cos + ai[m]*sin
    float ar[16], ai[16], zfr[16], zfi[16];
    #pragma unroll
    for (int j = 0; j < 16; j++) {
        int m = hh * 16 + j;
        float hr = Hf[m], hi = Hf[32 + m];
        float a1 = __ldg(&g_w1tr[m * HID + ch]);
        float b1 = __ldg(&g_w1ti[m * HID + ch]);
        float km = (m == 0) ? (1.0f / SLEN) : (2.0f / SLEN);
        ar[j] = km * (hr * a1 - hi * b1);
        float oi = km * (hr * b1 + hi * a1);
        ai[j] = (m == 0) ? 0.0f : -oi;         // DC imag dropped by irfft
        zfr[j] = 0.0f; zfi[j] = 0.0f;
    }

    const float4* tC = reinterpret_cast<const float4*>(g_tabC);
    const float4* tS = reinterpret_cast<const float4*>(g_tabS);
    int base = hh * 4;                         // float4 offset inside 8-float4 row

    // special points s=0 and s=512 (sin == 0 there)
    {
        float c0[16], c5[16];
        #pragma unroll
        for (int q = 0; q < 4; q++) {
            float4 a = __ldg(&tC[0 * 8 + base + q]);
            float4 c = __ldg(&tC[512 * 8 + base + q]);
            c0[4*q+0]=a.x; c0[4*q+1]=a.y; c0[4*q+2]=a.z; c0[4*q+3]=a.w;
            c5[4*q+0]=c.x; c5[4*q+1]=c.y; c5[4*q+2]=c.z; c5[4*q+3]=c.w;
        }
        float u0 = 0.0f, u5 = 0.0f;
        #pragma unroll
        for (int j = 0; j < 16; j++) {
            u0 = fmaf(ar[j], c0[j], u0);
            u5 = fmaf(ar[j], c5[j], u5);
        }
        u0 += __shfl_xor_sync(0xffffffffu, u0, 16);
        u5 += __shfl_xor_sync(0xffffffffu, u5, 16);
        float z0 = gelu_exact(u0), z5 = gelu_exact(u5);
        #pragma unroll
        for (int j = 0; j < 16; j++)
            zfr[j] = fmaf(z0, c0[j], fmaf(z5, c5[j], zfr[j]));
    }

    // paired points s=p and s=1024-p
    for (int p = 1; p <= 511; p++) {
        float c[16], sn[16];
        #pragma unroll
        for (int q = 0; q < 4; q++) {
            float4 a = __ldg(&tC[p * 8 + base + q]);
            float4 s = __ldg(&tS[p * 8 + base + q]);
            c [4*q+0]=a.x; c [4*q+1]=a.y; c [4*q+2]=a.z; c [4*q+3]=a.w;
            sn[4*q+0]=s.x; sn[4*q+1]=s.y; sn[4*q+2]=s.z; sn[4*q+3]=s.w;
        }
        float u = 0.0f, v = 0.0f;
        #pragma unroll
        for (int j = 0; j < 16; j++) {
            u = fmaf(ar[j], c[j], u);
            v = fmaf(ai[j], sn[j], v);
        }
        float ya = u + v, yb = u - v;          // y(p), y(1024-p) partials
        ya += __shfl_xor_sync(0xffffffffu, ya, 16);
        yb += __shfl_xor_sync(0xffffffffu, yb, 16);
        float ymine = hh ? yb : ya;
        float zmine = gelu_exact(ymine);
        float zoth  = __shfl_xor_sync(0xffffffffu, zmine, 16);
        float z0 = hh ? zoth : zmine;
        float z1 = hh ? zmine : zoth;
        float zp = z0 + z1, zd = z1 - z0;
        #pragma unroll
        for (int j = 0; j < 16; j++) {
            zfr[j] = fmaf(zp, c[j],  zfr[j]);
            zfi[j] = fmaf(zd, sn[j], zfi[j]);  // Zfi = -(z0 - z1)*sin = (z1-z0)*sin
        }
    }

    #pragma unroll
    for (int j = 0; j < 16; j++) {
        int m = hh * 16 + j;
        g_Zf[((size_t)(m * 2 + 0) * NB + b) * HID + ch] = zfr[j];
        g_Zf[((size_t)(m * 2 + 1) * NB + b) * HID + ch] = zfi[j];
    }
}

// ---------------- K_mix: per-mode complex GEMM (B x 128) x (128 x 128) ----------------
__global__ __launch_bounds__(256, 2) void k_mix() {
    int m  = blockIdx.x;                       // mode
    int bt = blockIdx.y;                       // b-tile of 64
    __shared__ float Zr[64 * 33], Zi[64 * 33];
    __shared__ float Wr[32 * 128], Wi[32 * 128];
    int t = threadIdx.x;
    int bo_g = t >> 4, o_g = t & 15;
    int b0 = bo_g * 4, o0 = o_g * 8;

    float accr[4][8], acci[4][8];
    #pragma unroll
    for (int x = 0; x < 4; x++)
        #pragma unroll
        for (int y = 0; y < 8; y++) { accr[x][y] = 0.0f; acci[x][y] = 0.0f; }

    const float* Zsr = g_Zf + ((size_t)(m * 2 + 0) * NB + bt * 64) * HID;
    const float* Zsi = g_Zf + ((size_t)(m * 2 + 1) * NB + bt * 64) * HID;

    for (int i0 = 0; i0 < HID; i0 += 32) {
        __syncthreads();
        for (int idx = t; idx < 64 * 32; idx += 256) {
            int bb = idx >> 5, ic = idx & 31;
            Zr[bb * 33 + ic] = Zsr[bb * HID + i0 + ic];
            Zi[bb * 33 + ic] = Zsi[bb * HID + i0 + ic];
        }
        for (int idx = t; idx < 32 * 128; idx += 256) {
            int ic = idx >> 7, o = idx & 127;
            Wr[idx] = g_w2tr[((size_t)m * HID + i0 + ic) * HID + o];
            Wi[idx] = g_w2ti[((size_t)m * HID + i0 + ic) * HID + o];
        }
        __syncthreads();
        #pragma unroll 4
        for (int ic = 0; ic < 32; ic++) {
            float zr[4], zi[4];
            #pragma unroll
            for (int bb = 0; bb < 4; bb++) {
                zr[bb] = Zr[(b0 + bb) * 33 + ic];
                zi[bb] = Zi[(b0 + bb) * 33 + ic];
            }
            float wr[8], wi[8];
            #pragma unroll
            for (int q = 0; q < 2; q++) {
                float4 a = reinterpret_cast<const float4*>(&Wr[ic * 128 + o0])[q];
                float4 c = reinterpret_cast<const float4*>(&Wi[ic * 128 + o0])[q];
                wr[4*q+0]=a.x; wr[4*q+1]=a.y; wr[4*q+2]=a.z; wr[4*q+3]=a.w;
                wi[4*q+0]=c.x; wi[4*q+1]=c.y; wi[4*q+2]=c.z; wi[4*q+3]=c.w;
            }
            #pragma unroll
            for (int bb = 0; bb < 4; bb++)
                #pragma unroll
                for (int oo = 0; oo < 8; oo++) {
                    accr[bb][oo] = fmaf(zr[bb], wr[oo], fmaf(-zi[bb], wi[oo], accr[bb][oo]));
                    acci[bb][oo] = fmaf(zr[bb], wi[oo], fmaf( zi[bb], wr[oo], acci[bb][oo]));
                }
        }
    }
    #pragma unroll
    for (int bb = 0; bb < 4; bb++) {
        size_t rowr = ((size_t)(m * 2 + 0) * NB + bt * 64 + b0 + bb) * HID + o0;
        size_t rowi = ((size_t)(m * 2 + 1) * NB + bt * 64 + b0 + bb) * HID + o0;
        #pragma unroll
        for (int oo = 0; oo < 8; oo++) {
            g_of2[rowr + oo] = accr[bb][oo];
            g_of2[rowi + oo] = acci[bb][oo];
        }
    }
}

// ---------------- K_layer2: synth + gelu + mean ----------------
__global__ __launch_bounds__(256, 2) void k_layer2(float* __restrict__ out) {
    int b = blockIdx.x;
    int t = threadIdx.x;
    int lane = t & 31, w = t >> 5, hh = lane >> 4;
    int o = w * 16 + (lane & 15);

    float br[16], bi[16];
    #pragma unroll
    for (int j = 0; j < 16; j++) {
        int m = hh * 16 + j;
        float orr = __ldg(&g_of2[((size_t)(m * 2 + 0) * NB + b) * HID + o]);
        float oii = __ldg(&g_of2[((size_t)(m * 2 + 1) * NB + b) * HID + o]);
        float km = (m == 0) ? (1.0f / SLEN) : (2.0f / SLEN);
        br[j] = km * orr;
        bi[j] = (m == 0) ? 0.0f : -km * oii;
    }

    const float4* tC = reinterpret_cast<const float4*>(g_tabC);
    const float4* tS = reinterpret_cast<const float4*>(g_tabS);
    int base = hh * 4;
    float acc = 0.0f;

    {   // s=0 and s=512
        float c0[16], c5[16];
        #pragma unroll
        for (int q = 0; q < 4; q++) {
            float4 a = __ldg(&tC[0 * 8 + base + q]);
            float4 c = __ldg(&tC[512 * 8 + base + q]);
            c0[4*q+0]=a.x; c0[4*q+1]=a.y; c0[4*q+2]=a.z; c0[4*q+3]=a.w;
            c5[4*q+0]=c.x; c5[4*q+1]=c.y; c5[4*q+2]=c.z; c5[4*q+3]=c.w;
        }
        float u0 = 0.0f, u5 = 0.0f;
        #pragma unroll
        for (int j = 0; j < 16; j++) {
            u0 = fmaf(br[j], c0[j], u0);
            u5 = fmaf(br[j], c5[j], u5);
        }
        u0 += __shfl_xor_sync(0xffffffffu, u0, 16);
        u5 += __shfl_xor_sync(0xffffffffu, u5, 16);
        acc += gelu_exact(u0) + gelu_exact(u5);
    }

    for (int p = 1; p <= 511; p++) {
        float c[16], sn[16];
        #pragma unroll
        for (int q = 0; q < 4; q++) {
            float4 a = __ldg(&tC[p * 8 + base + q]);
            float4 s = __ldg(&tS[p * 8 + base + q]);
            c [4*q+0]=a.x; c [4*q+1]=a.y; c [4*q+2]=a.z; c [4*q+3]=a.w;
            sn[4*q+0]=s.x; sn[4*q+1]=s.y; sn[4*q+2]=s.z; sn[4*q+3]=s.w;
        }
        float u = 0.0f, v = 0.0f;
        #pragma unroll
        for (int j = 0; j < 16; j++) {
            u = fmaf(br[j], c[j], u);
            v = fmaf(bi[j], sn[j], v);
        }
        float ya = u + v, yb = u - v;
        ya += __shfl_xor_sync(0xffffffffu, ya, 16);
        yb += __shfl_xor_sync(0xffffffffu, yb, 16);
        float ymine = hh ? yb : ya;
        float zmine = gelu_exact(ymine);
        float zoth  = __shfl_xor_sync(0xffffffffu, zmine, 16);
        acc += zmine + zoth;
    }

    if (hh == 0) out[(size_t)b * HID + o] = acc * (1.0f / SLEN);
}

// ---------------- launch ----------------
extern "C" void kernel_launch(void* const* d_in, const int* in_sizes, int n_in,
                              void* d_out, int out_size) {
    // identify inputs by size (order within a size group preserved: r then i)
    const float* hin = nullptr;
    const float* w1p[2] = {nullptr, nullptr};
    const float* w2p[2] = {nullptr, nullptr};
    int n1 = 0, n2 = 0;
    for (int i = 0; i < n_in; i++) {
        int sz = in_sizes[i];
        const float* p = (const float*)d_in[i];
        if (sz == NB * SLEN) hin = p;
        else if (sz == HID * NM) { if (n1 < 2) w1p[n1++] = p; }
        else if (sz == HID * HID * NM) { if (n2 < 2) w2p[n2++] = p; }
    }
    float* out = (float*)d_out;

    k_tab<<<(SLEN * NM + 255) / 256, 256>>>();
    k_w<<<(NM * HID * HID + 255) / 256, 256>>>(w1p[0], w1p[1], w2p[0], w2p[1]);
    k_layer1<<<NB, 256>>>(hin);
    dim3 g3(NM, 16);
    k_mix<<<g3, 256>>>();
    k_layer2<<<NB, 256>>>(out);
}

// round 4
// speedup vs baseline: 1.7356x; 1.7356x over previous
#include <cuda_runtime.h>
#include <math.h>

#define SLEN 1024
#define NM   32
#define HID  128
#define NB   1024

// ---------------- scratch (static device memory; no allocation) ----------------
__device__ float g_tabC[SLEN*NM];          // cos(2*pi*m*s/S), [s][m]
__device__ float g_tabS[SLEN*NM];          // sin(2*pi*m*s/S), [s][m]
__device__ float g_w1tr[NM*HID];           // [m][ch]
__device__ float g_w1ti[NM*HID];
__device__ float g_w2tr[NM*HID*HID];       // [m][i][o]
__device__ float g_w2ti[NM*HID*HID];
__device__ float g_Zf [2*NM*NB*HID];       // [(m*2+ri)][b][ch]
__device__ float g_of2[2*NM*NB*HID];       // [(m*2+ri)][b][o]

// Fast exact-enough GELU: Abramowitz-Stegun 7.1.26 erf (max abs err 1.5e-7),
// branchless, 2 MUFU (rcp + ex2).
__device__ __forceinline__ float gelu_fast(float x) {
    float q    = fabsf(x) * 0.70710678118654752f;
    float t    = __fdividef(1.0f, fmaf(0.3275911f, q, 1.0f));
    float poly = fmaf(fmaf(fmaf(fmaf(1.061405429f, t, -1.453152027f),
                               t, 1.421413741f),
                          t, -0.284496736f),
                      t, 0.254829592f) * t;
    float er   = 1.0f - poly * __expf(-q * q);
    float phi  = fmaf(copysignf(er, x), 0.5f, 0.5f);
    return x * phi;
}

// ---------------- K_tab: exact trig tables ----------------
__global__ void k_tab() {
    int idx = blockIdx.x * blockDim.x + threadIdx.x;
    if (idx >= SLEN * NM) return;
    int s = idx >> 5, m = idx & 31;
    int k = (s * m) & (SLEN - 1);              // exact phase reduction
    float x = (float)k * (1.0f / 512.0f);      // angle = pi * x = 2*pi*k/1024
    float sv, cv;
    sincospif(x, &sv, &cv);
    g_tabC[idx] = cv;
    g_tabS[idx] = sv;
}

// ---------------- K_w: weight transposes ----------------
__global__ void k_w(const float* __restrict__ w1r, const float* __restrict__ w1i,
                    const float* __restrict__ w2r, const float* __restrict__ w2i) {
    int tid = blockIdx.x * blockDim.x + threadIdx.x;
    if (tid < NM * HID) {                      // w1 src: [ch][m]
        int ch = tid >> 5, m = tid & 31;
        g_w1tr[m * HID + ch] = w1r[tid];
        g_w1ti[m * HID + ch] = w1i[tid];
    }
    if (tid < NM * HID * HID) {                // w2 src: [i][o][m]
        int m = tid & 31; int io = tid >> 5;
        int i = io >> 7;  int o = io & 127;
        g_w2tr[(m * HID + i) * HID + o] = w2r[tid];
        g_w2ti[(m * HID + i) * HID + o] = w2i[tid];
    }
}

// ---------------- K_layer1: DFT(h) -> mix w1 -> synth+gelu+analyze (fused) ----------------
// Block = one batch row b. 256 threads.
// Warp w handles channels [16w, 16w+16); lane>>4 selects mode-half (16 modes each).
// Quarter-wave symmetry: iteration p covers spatial points {p, 1024-p, 512+p, 512-p}.
__global__ __launch_bounds__(256, 2) void k_layer1(const float* __restrict__ hin) {
    __shared__ float h_sm[SLEN];
    __shared__ float red[64 * 4];
    __shared__ float Hf[64];                   // [0:32) real, [32:64) imag
    int b = blockIdx.x;
    int t = threadIdx.x;

    // stage h row
    {
        const float4* src = reinterpret_cast<const float4*>(hin + (size_t)b * SLEN);
        float4* dst = reinterpret_cast<float4*>(h_sm);
        for (int j = t; j < SLEN / 4; j += 256) dst[j] = src[j];
    }
    __syncthreads();

    // forward DFT of h: Hfr[m] = sum h*cos, Hfi[m] = -sum h*sin
    {
        int out = t & 63, seg = t >> 6;
        int m = out & 31; int isI = out >> 5;
        const float* tab = isI ? g_tabS : g_tabC;
        float acc = 0.0f;
        int s0 = seg * 256;
        #pragma unroll 8
        for (int j = 0; j < 256; j++) {
            int s = s0 + j;
            acc = fmaf(h_sm[s], __ldg(&tab[s * NM + m]), acc);
        }
        red[out * 4 + seg] = acc;
    }
    __syncthreads();
    if (t < 64) {
        float v = red[t * 4] + red[t * 4 + 1] + red[t * 4 + 2] + red[t * 4 + 3];
        Hf[t] = (t >= 32) ? -v : v;
    }
    __syncthreads();

    int lane = t & 31;
    int w    = t >> 5;
    int hh   = lane >> 4;                      // mode-half
    int ch   = w * 16 + (lane & 15);
    float sgn = hh ? -1.0f : 1.0f;             // parity fold sign

    // synthesis coefficients: y(s) = sum ar[m]*cos + ai[m]*sin
    float ar[16], ai[16], zfr[16], zfi[16];
    #pragma unroll
    for (int j = 0; j < 16; j++) {
        int m = hh * 16 + j;
        float hr = Hf[m], hi = Hf[32 + m];
        float a1 = __ldg(&g_w1tr[m * HID + ch]);
        float b1 = __ldg(&g_w1ti[m * HID + ch]);
        float km = (m == 0) ? (1.0f / SLEN) : (2.0f / SLEN);
        ar[j] = km * (hr * a1 - hi * b1);
        float oi = km * (hr * b1 + hi * a1);
        ai[j] = (m == 0) ? 0.0f : -oi;         // DC imag dropped by irfft
        zfr[j] = 0.0f; zfi[j] = 0.0f;
    }

    const float4* tC = reinterpret_cast<const float4*>(g_tabC);
    const float4* tS = reinterpret_cast<const float4*>(g_tabS);
    int base = hh * 4;                         // float4 offset inside 8-float4 row

    // special points s=0 and s=512 (sin == 0 there)
    {
        float c0[16], c5[16];
        #pragma unroll
        for (int q = 0; q < 4; q++) {
            float4 a = __ldg(&tC[0 * 8 + base + q]);
            float4 c = __ldg(&tC[512 * 8 + base + q]);
            c0[4*q+0]=a.x; c0[4*q+1]=a.y; c0[4*q+2]=a.z; c0[4*q+3]=a.w;
            c5[4*q+0]=c.x; c5[4*q+1]=c.y; c5[4*q+2]=c.z; c5[4*q+3]=c.w;
        }
        float u0 = 0.0f, u5 = 0.0f;
        #pragma unroll
        for (int j = 0; j < 16; j++) {
            u0 = fmaf(ar[j], c0[j], u0);
            u5 = fmaf(ar[j], c5[j], u5);
        }
        u0 += __shfl_xor_sync(0xffffffffu, u0, 16);
        u5 += __shfl_xor_sync(0xffffffffu, u5, 16);
        float z0 = gelu_fast(u0), z5 = gelu_fast(u5);
        #pragma unroll
        for (int j = 0; j < 16; j++)
            zfr[j] = fmaf(z0, c0[j], fmaf(z5, c5[j], zfr[j]));
    }

    // special pair s=256 / s=768 (old half-wave symmetry)
    {
        float c[16], sn[16];
        #pragma unroll
        for (int q = 0; q < 4; q++) {
            float4 a = __ldg(&tC[256 * 8 + base + q]);
            float4 s = __ldg(&tS[256 * 8 + base + q]);
            c [4*q+0]=a.x; c [4*q+1]=a.y; c [4*q+2]=a.z; c [4*q+3]=a.w;
            sn[4*q+0]=s.x; sn[4*q+1]=s.y; sn[4*q+2]=s.z; sn[4*q+3]=s.w;
        }
        float u = 0.0f, v = 0.0f;
        #pragma unroll
        for (int j = 0; j < 16; j++) {
            u = fmaf(ar[j], c[j], u);
            v = fmaf(ai[j], sn[j], v);
        }
        float ya = u + v, yb = u - v;          // y(256), y(768)
        ya += __shfl_xor_sync(0xffffffffu, ya, 16);
        yb += __shfl_xor_sync(0xffffffffu, yb, 16);
        float ymine = hh ? yb : ya;
        float zmine = gelu_fast(ymine);
        float zoth  = __shfl_xor_sync(0xffffffffu, zmine, 16);
        float z0 = hh ? zoth : zmine;          // z(256)
        float z1 = hh ? zmine : zoth;          // z(768)
        float zp = z0 + z1, zd = z1 - z0;
        #pragma unroll
        for (int j = 0; j < 16; j++) {
            zfr[j] = fmaf(zp, c[j],  zfr[j]);
            zfi[j] = fmaf(zd, sn[j], zfi[j]);
        }
    }

    // quad points {p, 1024-p, 512+p, 512-p}, p = 1..255
    for (int p = 1; p <= 255; p++) {
        float c[16], sn[16];
        #pragma unroll
        for (int q = 0; q < 4; q++) {
            float4 a = __ldg(&tC[p * 8 + base + q]);
            float4 s = __ldg(&tS[p * 8 + base + q]);
            c [4*q+0]=a.x; c [4*q+1]=a.y; c [4*q+2]=a.z; c [4*q+3]=a.w;
            sn[4*q+0]=s.x; sn[4*q+1]=s.y; sn[4*q+2]=s.z; sn[4*q+3]=s.w;
        }
        // parity-split partial sums (even j <=> even mode m)
        float ue = 0.0f, uo = 0.0f, ve = 0.0f, vo = 0.0f;
        #pragma unroll
        for (int j = 0; j < 16; j += 2) {
            ue = fmaf(ar[j],   c[j],    ue);
            uo = fmaf(ar[j+1], c[j+1],  uo);
            ve = fmaf(ai[j],   sn[j],   ve);
            vo = fmaf(ai[j+1], sn[j+1], vo);
        }
        ue += __shfl_xor_sync(0xffffffffu, ue, 16);
        uo += __shfl_xor_sync(0xffffffffu, uo, 16);
        ve += __shfl_xor_sync(0xffffffffu, ve, 16);
        vo += __shfl_xor_sync(0xffffffffu, vo, 16);
        // hh=0 owns points {p, 1024-p}; hh=1 owns {512+p, 512-p}
        float U = fmaf(sgn, uo, ue);
        float V = fmaf(sgn, vo, ve);
        float ya = U + V;                      // z0 (t0) / z2 (t1)
        float yb = U - V;                      // z1 (t0) / z3 (t1)
        float za = gelu_fast(ya), zb = gelu_fast(yb);
        float sP = za + zb;                    // A (t0) / B (t1)
        float sM = zb - za;                    // C (t0) / D (t1)
        float oP = __shfl_xor_sync(0xffffffffu, sP, 16);
        float oM = __shfl_xor_sync(0xffffffffu, sM, 16);
        float A = hh ? oP : sP,  B = hh ? sP : oP;
        float C = hh ? oM : sM,  D = hh ? sM : oM;
        float rp = A + B, rm = A - B;          // cos weights: even / odd modes
        float ip = C + D, im = C - D;          // sin weights: even / odd modes
        #pragma unroll
        for (int j = 0; j < 16; j += 2) {
            zfr[j]   = fmaf(rp, c[j],    zfr[j]);
            zfi[j]   = fmaf(ip, sn[j],   zfi[j]);
            zfr[j+1] = fmaf(rm, c[j+1],  zfr[j+1]);
            zfi[j+1] = fmaf(im, sn[j+1], zfi[j+1]);
        }
    }

    #pragma unroll
    for (int j = 0; j < 16; j++) {
        int m = hh * 16 + j;
        g_Zf[((size_t)(m * 2 + 0) * NB + b) * HID + ch] = zfr[j];
        g_Zf[((size_t)(m * 2 + 1) * NB + b) * HID + ch] = zfi[j];
    }
}

// ---------------- K_mix: per-mode complex GEMM (B x 128) x (128 x 128) ----------------
__global__ __launch_bounds__(256, 2) void k_mix() {
    int m  = blockIdx.x;                       // mode
    int bt = blockIdx.y;                       // b-tile of 64
    __shared__ float Zr[64 * 33], Zi[64 * 33];
    __shared__ float Wr[32 * 128], Wi[32 * 128];
    int t = threadIdx.x;
    int bo_g = t >> 4, o_g = t & 15;
    int b0 = bo_g * 4, o0 = o_g * 8;

    float accr[4][8], acci[4][8];
    #pragma unroll
    for (int x = 0; x < 4; x++)
        #pragma unroll
        for (int y = 0; y < 8; y++) { accr[x][y] = 0.0f; acci[x][y] = 0.0f; }

    const float* Zsr = g_Zf + ((size_t)(m * 2 + 0) * NB + bt * 64) * HID;
    const float* Zsi = g_Zf + ((size_t)(m * 2 + 1) * NB + bt * 64) * HID;

    for (int i0 = 0; i0 < HID; i0 += 32) {
        __syncthreads();
        for (int idx = t; idx < 64 * 32; idx += 256) {
            int bb = idx >> 5, ic = idx & 31;
            Zr[bb * 33 + ic] = Zsr[bb * HID + i0 + ic];
            Zi[bb * 33 + ic] = Zsi[bb * HID + i0 + ic];
        }
        for (int idx = t; idx < 32 * 128; idx += 256) {
            int ic = idx >> 7, o = idx & 127;
            Wr[idx] = g_w2tr[((size_t)m * HID + i0 + ic) * HID + o];
            Wi[idx] = g_w2ti[((size_t)m * HID + i0 + ic) * HID + o];
        }
        __syncthreads();
        #pragma unroll 4
        for (int ic = 0; ic < 32; ic++) {
            float zr[4], zi[4];
            #pragma unroll
            for (int bb = 0; bb < 4; bb++) {
                zr[bb] = Zr[(b0 + bb) * 33 + ic];
                zi[bb] = Zi[(b0 + bb) * 33 + ic];
            }
            float wr[8], wi[8];
            #pragma unroll
            for (int q = 0; q < 2; q++) {
                float4 a = reinterpret_cast<const float4*>(&Wr[ic * 128 + o0])[q];
                float4 c = reinterpret_cast<const float4*>(&Wi[ic * 128 + o0])[q];
                wr[4*q+0]=a.x; wr[4*q+1]=a.y; wr[4*q+2]=a.z; wr[4*q+3]=a.w;
                wi[4*q+0]=c.x; wi[4*q+1]=c.y; wi[4*q+2]=c.z; wi[4*q+3]=c.w;
            }
            #pragma unroll
            for (int bb = 0; bb < 4; bb++)
                #pragma unroll
                for (int oo = 0; oo < 8; oo++) {
                    accr[bb][oo] = fmaf(zr[bb], wr[oo], fmaf(-zi[bb], wi[oo], accr[bb][oo]));
                    acci[bb][oo] = fmaf(zr[bb], wi[oo], fmaf( zi[bb], wr[oo], acci[bb][oo]));
                }
        }
    }
    #pragma unroll
    for (int bb = 0; bb < 4; bb++) {
        size_t rowr = ((size_t)(m * 2 + 0) * NB + bt * 64 + b0 + bb) * HID + o0;
        size_t rowi = ((size_t)(m * 2 + 1) * NB + bt * 64 + b0 + bb) * HID + o0;
        #pragma unroll
        for (int oo = 0; oo < 8; oo++) {
            g_of2[rowr + oo] = accr[bb][oo];
            g_of2[rowi + oo] = acci[bb][oo];
        }
    }
}

// ---------------- K_layer2: synth + gelu + mean (quad symmetry) ----------------
__global__ __launch_bounds__(256, 2) void k_layer2(float* __restrict__ out) {
    int b = blockIdx.x;
    int t = threadIdx.x;
    int lane = t & 31, w = t >> 5, hh = lane >> 4;
    int o = w * 16 + (lane & 15);
    float sgn = hh ? -1.0f : 1.0f;

    float br[16], bi[16];
    #pragma unroll
    for (int j = 0; j < 16; j++) {
        int m = hh * 16 + j;
        float orr = __ldg(&g_of2[((size_t)(m * 2 + 0) * NB + b) * HID + o]);
        float oii = __ldg(&g_of2[((size_t)(m * 2 + 1) * NB + b) * HID + o]);
        float km = (m == 0) ? (1.0f / SLEN) : (2.0f / SLEN);
        br[j] = km * orr;
        bi[j] = (m == 0) ? 0.0f : -km * oii;
    }

    const float4* tC = reinterpret_cast<const float4*>(g_tabC);
    const float4* tS = reinterpret_cast<const float4*>(g_tabS);
    int base = hh * 4;
    float acc = 0.0f;                          // per-thread partial (own points only)

    {   // s=0 (t0 adds) and s=512 (t1 adds)
        float c0[16], c5[16];
        #pragma unroll
        for (int q = 0; q < 4; q++) {
            float4 a = __ldg(&tC[0 * 8 + base + q]);
            float4 c = __ldg(&tC[512 * 8 + base + q]);
            c0[4*q+0]=a.x; c0[4*q+1]=a.y; c0[4*q+2]=a.z; c0[4*q+3]=a.w;
            c5[4*q+0]=c.x; c5[4*q+1]=c.y; c5[4*q+2]=c.z; c5[4*q+3]=c.w;
        }
        float u0 = 0.0f, u5 = 0.0f;
        #pragma unroll
        for (int j = 0; j < 16; j++) {
            u0 = fmaf(br[j], c0[j], u0);
            u5 = fmaf(br[j], c5[j], u5);
        }
        u0 += __shfl_xor_sync(0xffffffffu, u0, 16);
        u5 += __shfl_xor_sync(0xffffffffu, u5, 16);
        acc += gelu_fast(hh ? u5 : u0);
    }

    {   // s=256 (t0 adds) / s=768 (t1 adds)
        float c[16], sn[16];
        #pragma unroll
        for (int q = 0; q < 4; q++) {
            float4 a = __ldg(&tC[256 * 8 + base + q]);
            float4 s = __ldg(&tS[256 * 8 + base + q]);
            c [4*q+0]=a.x; c [4*q+1]=a.y; c [4*q+2]=a.z; c [4*q+3]=a.w;
            sn[4*q+0]=s.x; sn[4*q+1]=s.y; sn[4*q+2]=s.z; sn[4*q+3]=s.w;
        }
        float u = 0.0f, v = 0.0f;
        #pragma unroll
        for (int j = 0; j < 16; j++) {
            u = fmaf(br[j], c[j], u);
            v = fmaf(bi[j], sn[j], v);
        }
        float ya = u + v, yb = u - v;
        ya += __shfl_xor_sync(0xffffffffu, ya, 16);
        yb += __shfl_xor_sync(0xffffffffu, yb, 16);
        acc += gelu_fast(hh ? yb : ya);
    }

    for (int p = 1; p <= 255; p++) {
        float c[16], sn[16];
        #pragma unroll
        for (int q = 0; q < 4; q++) {
            float4 a = __ldg(&tC[p * 8 + base + q]);
            float4 s = __ldg(&tS[p * 8 + base + q]);
            c [4*q+0]=a.x; c [4*q+1]=a.y; c [4*q+2]=a.z; c [4*q+3]=a.w;
            sn[4*q+0]=s.x; sn[4*q+1]=s.y; sn[4*q+2]=s.z; sn[4*q+3]=s.w;
        }
        float ue = 0.0f, uo = 0.0f, ve = 0.0f, vo = 0.0f;
        #pragma unroll
        for (int j = 0; j < 16; j += 2) {
            ue = fmaf(br[j],   c[j],    ue);
            uo = fmaf(br[j+1], c[j+1],  uo);
            ve = fmaf(bi[j],   sn[j],   ve);
            vo = fmaf(bi[j+1], sn[j+1], vo);
        }
        ue += __shfl_xor_sync(0xffffffffu, ue, 16);
        uo += __shfl_xor_sync(0xffffffffu, uo, 16);
        ve += __shfl_xor_sync(0xffffffffu, ve, 16);
        vo += __shfl_xor_sync(0xffffffffu, vo, 16);
        float U = fmaf(sgn, uo, ue);
        float V = fmaf(sgn, vo, ve);
        acc += gelu_fast(U + V) + gelu_fast(U - V);
    }

    acc += __shfl_xor_sync(0xffffffffu, acc, 16);
    if (hh == 0) out[(size_t)b * HID + o] = acc * (1.0f / SLEN);
}

// ---------------- launch ----------------
extern "C" void kernel_launch(void* const* d_in, const int* in_sizes, int n_in,
                              void* d_out, int out_size) {
    // identify inputs by size (order within a size group preserved: r then i)
    const float* hin = nullptr;
    const float* w1p[2] = {nullptr, nullptr};
    const float* w2p[2] = {nullptr, nullptr};
    int n1 = 0, n2 = 0;
    for (int i = 0; i < n_in; i++) {
        int sz = in_sizes[i];
        const float* p = (const float*)d_in[i];
        if (sz == NB * SLEN) hin = p;
        else if (sz == HID * NM) { if (n1 < 2) w1p[n1++] = p; }
        else if (sz == HID * HID * NM) { if (n2 < 2) w2p[n2++] = p; }
    }
    float* out = (float*)d_out;

    k_tab<<<(SLEN * NM + 255) / 256, 256>>>();
    k_w<<<(NM * HID * HID + 255) / 256, 256>>>(w1p[0], w1p[1], w2p[0], w2p[1]);
    k_layer1<<<NB, 256>>>(hin);
    dim3 g3(NM, 16);
    k_mix<<<g3, 256>>>();
    k_layer2<<<NB, 256>>>(out);
}